// round 4
// baseline (speedup 1.0000x reference)
#include <cuda_runtime.h>

#define KK     3
#define CIN    16
#define COUT   16
#define HH     64
#define WW     64
#define BB     4

#define TILE_H 8          // output rows per block
#define BX     64
#define BY     2          // 128 threads; each thread: 4 rows x 2 packed channels
#define PX     4          // pixels (rows) per thread
#define FG     2          // output channels per block (1 packed f32x2 pair)

#define SC_N   (CIN * 9 * 10)                 // 1440 float2 / ull
#define SX_ROWS (TILE_H + 2)                  // 10
#define SX_N   (CIN * SX_ROWS * 66)           // 10560 floats
#define SMEM_BYTES (SC_N * 8 + SX_N * 4)      // 11520 + 42240 = 53760

typedef unsigned long long ull;

// ---------------- Blackwell packed f32x2 helpers ----------------
__device__ __forceinline__ ull pk2s(float v) {            // (v, v)
    ull r; asm("mov.b64 %0, {%1, %1};" : "=l"(r) : "f"(v)); return r;
}
__device__ __forceinline__ void upk2(ull v, float& lo, float& hi) {
    asm("mov.b64 {%0, %1}, %2;" : "=f"(lo), "=f"(hi) : "l"(v));
}
__device__ __forceinline__ ull pk2(float lo, float hi) {
    ull r; asm("mov.b64 %0, {%1, %2};" : "=l"(r) : "f"(lo), "f"(hi)); return r;
}
__device__ __forceinline__ ull ffma2(ull a, ull b, ull c) {
    ull d; asm("fma.rn.f32x2 %0, %1, %2, %3;" : "=l"(d) : "l"(a), "l"(b), "l"(c)); return d;
}
__device__ __forceinline__ ull fmul2(ull a, ull b) {
    ull d; asm("mul.rn.f32x2 %0, %1, %2;" : "=l"(d) : "l"(a), "l"(b)); return d;
}
__device__ __forceinline__ ull fadd2(ull a, ull b) {
    ull d; asm("add.rn.f32x2 %0, %1, %2;" : "=l"(d) : "l"(a), "l"(b)); return d;
}
__device__ __forceinline__ float frcp(float x) {
    float r; asm("rcp.approx.ftz.f32 %0, %1;" : "=f"(r) : "f"(x)); return r;
}

// Dynamic SMEM:
//  sC: packed coefficients for this block's 2 output channels (f0, f0+1).
//      Per (c, p): 10 float2: k=0..5 A-pair coefs, k=6..9 B-pair coefs.
//  sX: all 16 input-channel tiles, 10 rows x 66 cols (zero-padded halo).
__global__ __launch_bounds__(BX * BY)
void kaconv_kernel(const float* __restrict__ x,
                   const float* __restrict__ A,
                   const float* __restrict__ Bc,
                   float* __restrict__ out) {
    extern __shared__ __align__(16) char smem_raw[];
    ull*   sC = reinterpret_cast<ull*>(smem_raw);
    float* sX = reinterpret_cast<float*>(smem_raw + SC_N * 8);

    const int tx  = threadIdx.x;
    const int ty  = threadIdx.y;
    const int tid = ty * BX + tx;
    const int h0  = blockIdx.x * TILE_H;
    const int b   = blockIdx.y;
    const int f0  = blockIdx.z * FG;

    // ---- stage packed coefficients ----
    float2* sCf = reinterpret_cast<float2*>(sC);
    for (int i = tid; i < SC_N; i += BX * BY) {
        int ii = i;
        const int k = ii % 10; ii /= 10;
        const int p = ii % 9;
        const int c = ii / 9;
        float lo, hi;
        if (k < 6) {
            lo = A[(( f0      * CIN + c) * 9 + p) * 6 + k];
            hi = A[(((f0 + 1) * CIN + c) * 9 + p) * 6 + k];
        } else {
            const int j = k - 6;
            lo = Bc[(( f0      * CIN + c) * 9 + p) * 4 + j];
            hi = Bc[(((f0 + 1) * CIN + c) * 9 + p) * 4 + j];
        }
        sCf[i] = make_float2(lo, hi);
    }

    // ---- stage all 16 input-channel tiles with zero-padded halo ----
    for (int i = tid; i < SX_N; i += BX * BY) {
        const int col = i % 66;
        const int r   = (i / 66) % SX_ROWS;
        const int c   = i / (66 * SX_ROWS);
        const int gh  = h0 + r - 1;
        const int gw  = col - 1;
        float v = 0.0f;
        if (gh >= 0 && gh < HH && gw >= 0 && gw < WW)
            v = x[((b * CIN + c) * HH + gh) * WW + gw];
        sX[(c * SX_ROWS + r) * 66 + col] = v;
    }
    __syncthreads();

    const ulonglong2* sC2 = reinterpret_cast<const ulonglong2*>(sC);
    const ull ABSM = 0x7FFFFFFF7FFFFFFFull;
    const ull ONE2 = 0x3F8000003F800000ull;   // (1.0f, 1.0f)

    // 4 pixels per thread: rows h0 + 4*ty + (0..3), col tx; one f-pair
    ull acc[PX];
    #pragma unroll
    for (int i = 0; i < PX; i++) acc[i] = 0ull;

    #pragma unroll 1
    for (int c = 0; c < CIN; c++) {
        // 6 rows x 3 cols register window covers all 4 pixels' 3x3 windows
        float xr[PX + 2][3];
        #pragma unroll
        for (int r = 0; r < PX + 2; r++)
            #pragma unroll
            for (int j = 0; j < 3; j++)
                xr[r][j] = sX[(c * SX_ROWS + PX * ty + r) * 66 + (tx + j)];

        const ulonglong2* pc = sC2 + c * 45;   // 5 ulonglong2 per (c,p)
        #pragma unroll
        for (int p = 0; p < 9; p++) {
            const int di = p / 3, dj = p % 3;
            const ulonglong2 u0 = pc[p * 5 + 0];  // {A0, A1}
            const ulonglong2 u1 = pc[p * 5 + 1];  // {A2, A3}
            const ulonglong2 u2 = pc[p * 5 + 2];  // {A4, A5}
            const ulonglong2 u3 = pc[p * 5 + 3];  // {B1, B2}
            const ulonglong2 u4 = pc[p * 5 + 4];  // {B3, B4}

            #pragma unroll
            for (int py = 0; py < PX; py++) {
                const ull X = pk2s(xr[py + di][dj]);

                // P = a0 + a1 x + ... + a5 x^5  (Horner, packed over f-pair)
                ull P = ffma2(u2.y, X, u2.x);
                P = ffma2(P, X, u1.y);
                P = ffma2(P, X, u1.x);
                P = ffma2(P, X, u0.y);
                P = ffma2(P, X, u0.x);

                // S = x*(b1 + x*(b2 + x*(b3 + x*b4)))
                ull T = ffma2(u4.y, X, u4.x);
                T = ffma2(T, X, u3.y);
                T = ffma2(T, X, u3.x);
                T = fmul2(T, X);

                // Q = 1 + |S|; R = 1/Q (per scalar via MUFU)
                const ull Qp = fadd2(ONE2, T & ABSM);
                float q0f, q1f; upk2(Qp, q0f, q1f);
                const ull R = pk2(frcp(q0f), frcp(q1f));

                acc[py] = ffma2(P, R, acc[py]);
            }
        }
    }

    // ---- write 4 pixels x 2 channels ----
    const int hA = h0 + PX * ty;
    const int w  = tx;
    float* op = out + ((b * COUT + f0) * HH + hA) * WW + w;
    #pragma unroll
    for (int py = 0; py < PX; py++) {
        float lo, hi;
        upk2(acc[py], lo, hi);
        op[py * WW]           = lo;
        op[HH * WW + py * WW] = hi;
    }
}

extern "C" void kernel_launch(void* const* d_in, const int* in_sizes, int n_in,
                              void* d_out, int out_size) {
    const float* x  = (const float*)d_in[0];
    const float* A  = (const float*)d_in[1];
    const float* Bc = (const float*)d_in[2];
    float* out = (float*)d_out;

    static int configured = 0;
    if (!configured) {
        cudaFuncSetAttribute(kaconv_kernel,
                             cudaFuncAttributeMaxDynamicSharedMemorySize,
                             SMEM_BYTES);
        configured = 1;
    }

    dim3 grid(HH / TILE_H, BB, COUT / FG);   // (8, 4, 8) = 256 blocks
    dim3 block(BX, BY, 1);                   // 128 threads
    kaconv_kernel<<<grid, block, SMEM_BYTES>>>(x, A, Bc, out);
}

// round 5
// speedup vs baseline: 1.2000x; 1.2000x over previous
#include <cuda_runtime.h>

#define KK     3
#define CIN    16
#define COUT   16
#define HH     64
#define WW     64
#define BB     4

#define TILE_H 4          // output rows per block
#define BX     64
#define BY     2          // 128 threads; each thread: 2 rows, 1 packed f-pair
#define PX     2
#define FG     2          // output channels per block
#define CHALF  8          // input channels per block (CIN split in 2)

#define SX_ROWS (TILE_H + 2)                 // 6
#define NOUT    (BB * COUT * HH * WW)        // 1,048,576

typedef unsigned long long ull;

// partial sums: [2][B][COUT][H][W]
__device__ float g_partial[2 * NOUT];

// ---------------- Blackwell packed f32x2 helpers ----------------
__device__ __forceinline__ ull pk2s(float v) {            // (v, v)
    ull r; asm("mov.b64 %0, {%1, %1};" : "=l"(r) : "f"(v)); return r;
}
__device__ __forceinline__ void upk2(ull v, float& lo, float& hi) {
    asm("mov.b64 {%0, %1}, %2;" : "=f"(lo), "=f"(hi) : "l"(v));
}
__device__ __forceinline__ ull pk2(float lo, float hi) {
    ull r; asm("mov.b64 %0, {%1, %2};" : "=l"(r) : "f"(lo), "f"(hi)); return r;
}
__device__ __forceinline__ ull ffma2(ull a, ull b, ull c) {
    ull d; asm("fma.rn.f32x2 %0, %1, %2, %3;" : "=l"(d) : "l"(a), "l"(b), "l"(c)); return d;
}
__device__ __forceinline__ ull fmul2(ull a, ull b) {
    ull d; asm("mul.rn.f32x2 %0, %1, %2;" : "=l"(d) : "l"(a), "l"(b)); return d;
}
__device__ __forceinline__ ull fadd2(ull a, ull b) {
    ull d; asm("add.rn.f32x2 %0, %1, %2;" : "=l"(d) : "l"(a), "l"(b)); return d;
}
__device__ __forceinline__ float frcp(float x) {
    float r; asm("rcp.approx.ftz.f32 %0, %1;" : "=f"(r) : "f"(x)); return r;
}

// Static SMEM (18.4 KB):
//  sC: packed coefficients, this block's f-pair x its 8 input channels:
//      per (c,p): 10 float2 (6 A-pairs, 4 B-pairs) -> 720 float2 = 5760 B
//  sX: 8 input-channel tiles, 6 rows x 66 cols = 12672 B
__global__ __launch_bounds__(BX * BY)
void kaconv_kernel(const float* __restrict__ x,
                   const float* __restrict__ A,
                   const float* __restrict__ Bc) {
    __shared__ __align__(16) ull  sC[CHALF * 9 * 10];  // 720 slots = 5760 B
    __shared__ float              sX[CHALF * SX_ROWS * 66];

    const int tx  = threadIdx.x;
    const int ty  = threadIdx.y;
    const int tid = ty * BX + tx;
    const int h0  = blockIdx.x * TILE_H;
    const int b   = blockIdx.y;
    const int f0  = (blockIdx.z >> 1) * FG;
    const int ch  = blockIdx.z & 1;            // which c-half
    const int c0  = ch * CHALF;

    // ---- stage packed coefficients for channels c0..c0+7 ----
    float2* sCf = reinterpret_cast<float2*>(sC);
    for (int i = tid; i < CHALF * 9 * 10; i += BX * BY) {
        int ii = i;
        const int k = ii % 10; ii /= 10;
        const int p = ii % 9;
        const int c = c0 + ii / 9;
        float lo, hi;
        if (k < 6) {
            lo = A[(( f0      * CIN + c) * 9 + p) * 6 + k];
            hi = A[(((f0 + 1) * CIN + c) * 9 + p) * 6 + k];
        } else {
            const int j = k - 6;
            lo = Bc[(( f0      * CIN + c) * 9 + p) * 4 + j];
            hi = Bc[(((f0 + 1) * CIN + c) * 9 + p) * 4 + j];
        }
        sCf[i] = make_float2(lo, hi);
    }

    // ---- stage 8 input-channel tiles with zero-padded halo ----
    for (int i = tid; i < CHALF * SX_ROWS * 66; i += BX * BY) {
        const int col = i % 66;
        const int r   = (i / 66) % SX_ROWS;
        const int cl  = i / (66 * SX_ROWS);
        const int gh  = h0 + r - 1;
        const int gw  = col - 1;
        float v = 0.0f;
        if (gh >= 0 && gh < HH && gw >= 0 && gw < WW)
            v = x[((b * CIN + c0 + cl) * HH + gh) * WW + gw];
        sX[(cl * SX_ROWS + r) * 66 + col] = v;
    }
    __syncthreads();

    const ulonglong2* sC2 = reinterpret_cast<const ulonglong2*>(sC);
    const ull ABSM = 0x7FFFFFFF7FFFFFFFull;
    const ull ONE2 = 0x3F8000003F800000ull;   // (1.0f, 1.0f)

    ull acc0 = 0ull, acc1 = 0ull;

    #pragma unroll 1
    for (int c = 0; c < CHALF; c++) {
        // 4 rows x 3 cols register window covers both pixels' 3x3 windows
        float xr[PX + 2][3];
        #pragma unroll
        for (int r = 0; r < PX + 2; r++)
            #pragma unroll
            for (int j = 0; j < 3; j++)
                xr[r][j] = sX[(c * SX_ROWS + PX * ty + r) * 66 + (tx + j)];

        const ulonglong2* pc = sC2 + c * 45;   // 5 ulonglong2 per (c,p)
        #pragma unroll
        for (int p = 0; p < 9; p++) {
            const int di = p / 3, dj = p % 3;
            const ulonglong2 u0 = pc[p * 5 + 0];  // {A0, A1}
            const ulonglong2 u1 = pc[p * 5 + 1];  // {A2, A3}
            const ulonglong2 u2 = pc[p * 5 + 2];  // {A4, A5}
            const ulonglong2 u3 = pc[p * 5 + 3];  // {B1, B2}
            const ulonglong2 u4 = pc[p * 5 + 4];  // {B3, B4}

            #pragma unroll
            for (int py = 0; py < PX; py++) {
                const ull X = pk2s(xr[py + di][dj]);

                // P = a0 + ... + a5 x^5 (Horner, packed over f-pair)
                ull P = ffma2(u2.y, X, u2.x);
                P = ffma2(P, X, u1.y);
                P = ffma2(P, X, u1.x);
                P = ffma2(P, X, u0.y);
                P = ffma2(P, X, u0.x);

                // S = x*(b1 + x*(b2 + x*(b3 + x*b4)))
                ull T = ffma2(u4.y, X, u4.x);
                T = ffma2(T, X, u3.y);
                T = ffma2(T, X, u3.x);
                T = fmul2(T, X);

                // Q = 1 + |S|; R = 1/Q
                const ull Qp = fadd2(ONE2, T & ABSM);
                float q0f, q1f; upk2(Qp, q0f, q1f);
                const ull R = pk2(frcp(q0f), frcp(q1f));

                if (py == 0) acc0 = ffma2(P, R, acc0);
                else         acc1 = ffma2(P, R, acc1);
            }
        }
    }

    // ---- write partials: 2 pixels x 2 channels ----
    const int hA = h0 + PX * ty;
    const int w  = tx;
    float a0, a1, b0, b1;
    upk2(acc0, a0, a1);
    upk2(acc1, b0, b1);
    float* op = g_partial + ch * NOUT + ((b * COUT + f0) * HH + hA) * WW + w;
    op[0]                = a0;
    op[WW]               = b0;
    op[HH * WW]          = a1;
    op[HH * WW + WW]     = b1;
}

// ---- combine: out = partial[0] + partial[1], float4 vectorized ----
__global__ __launch_bounds__(256)
void combine_kernel(float* __restrict__ out) {
    const int i = blockIdx.x * 256 + threadIdx.x;       // float4 index
    const float4* p0 = reinterpret_cast<const float4*>(g_partial);
    const float4* p1 = reinterpret_cast<const float4*>(g_partial + NOUT);
    float4 a = p0[i], b = p1[i];
    float4 r;
    r.x = a.x + b.x; r.y = a.y + b.y; r.z = a.z + b.z; r.w = a.w + b.w;
    reinterpret_cast<float4*>(out)[i] = r;
}

extern "C" void kernel_launch(void* const* d_in, const int* in_sizes, int n_in,
                              void* d_out, int out_size) {
    const float* x  = (const float*)d_in[0];
    const float* A  = (const float*)d_in[1];
    const float* Bc = (const float*)d_in[2];
    float* out = (float*)d_out;

    dim3 grid(HH / TILE_H, BB, (COUT / FG) * 2);   // (16, 4, 16) = 1024 blocks
    dim3 block(BX, BY, 1);                          // 128 threads
    kaconv_kernel<<<grid, block>>>(x, A, Bc);

    combine_kernel<<<(NOUT / 4) / 256, 256>>>(out); // 1024 blocks x 256 thr
}